// round 10
// baseline (speedup 1.0000x reference)
#include <cuda_runtime.h>
#include <math.h>
#include <stdint.h>

#define BB 2
#define SS_ 2048
#define DD 2048
#define HH 16
#define HD 128
#define M_TOT (BB * SS_)     // 4096
#define N_QKV (3 * DD)       // 6144

__device__ float g_qkv[M_TOT * N_QKV];   // (b*s, 3*d) raw fp32 qkv
__device__ float g_att[M_TOT * DD];      // (b, s, d) attention out (tf32-rounded)
__device__ float g_x [M_TOT * DD];       // x rounded to tf32
__device__ float g_w1[DD * N_QKV];       // W_qkv rounded to tf32
__device__ float g_w2[DD * DD];          // W_out rounded to tf32

__device__ __forceinline__ uint32_t f2tf(float f) {
    uint32_t u;
    asm("cvt.rna.tf32.f32 %0, %1;" : "=r"(u) : "f"(f));
    return u;
}

__device__ __forceinline__ void mma_tf32(float* d, const uint32_t* a, const uint32_t* b) {
    asm volatile(
        "mma.sync.aligned.m16n8k8.row.col.f32.tf32.tf32.f32 "
        "{%0,%1,%2,%3}, {%4,%5,%6,%7}, {%8,%9}, {%0,%1,%2,%3};\n"
        : "+f"(d[0]), "+f"(d[1]), "+f"(d[2]), "+f"(d[3])
        : "r"(a[0]), "r"(a[1]), "r"(a[2]), "r"(a[3]), "r"(b[0]), "r"(b[1]));
}

__device__ __forceinline__ void cp16(uint32_t saddr, const float* gptr) {
    asm volatile("cp.async.cg.shared.global [%0], [%1], 16;" :: "r"(saddr), "l"(gptr));
}

// ---------------------------------------------------------------------------
// Prep: elementwise rna round fp32 -> tf32 bits (stored as float)
// ---------------------------------------------------------------------------
__global__ __launch_bounds__(256) void cvt_tf32_kernel(
    const float* __restrict__ src, float* __restrict__ dst, int n4)
{
    int stride = gridDim.x * blockDim.x;
    for (int i = blockIdx.x * blockDim.x + threadIdx.x; i < n4; i += stride) {
        float4 v = reinterpret_cast<const float4*>(src)[i];
        uint4 u = make_uint4(f2tf(v.x), f2tf(v.y), f2tf(v.z), f2tf(v.w));
        reinterpret_cast<uint4*>(dst)[i] = u;
    }
}

// ===========================================================================
// TF32 mma.sync GEMM. Block 128x256, 8 warps (2m x 4n), warp tile 64x64.
// Inputs pre-rounded tf32. A: LDG->STS fragment-major (LDS.128 consume).
// B: cp.async.cg direct global->smem, layout [(ks*2+reg)*4+c][264] so 16B
// global chunks land contiguously; LDS.32 consume, conflict-free both sides.
// 1 CTA/SM, unconstrained regs (R8 lesson: forcing occupancy spills).
// ===========================================================================
#define GBM 128
#define GBN 256
#define GBK 32
#define AFRAG_FLOATS 4224                  // 32 frags * 132
#define BFRAG_FLOATS 8448                  // 32 rows * 264
#define STAGE_FLOATS (AFRAG_FLOATS + BFRAG_FLOATS)
#define GEMM_SMEM_BYTES (2 * STAGE_FLOATS * 4)   // 101376

__global__ __launch_bounds__(256) void gemm_tf32_kernel(
    const float* __restrict__ A, const float* __restrict__ W,
    const float* __restrict__ bias, float* __restrict__ C,
    int M, int N, int K)
{
    extern __shared__ float sh[];
    uint32_t smb;
    asm("{ .reg .u64 t; cvta.to.shared.u64 t, %1; cvt.u32.u64 %0, t; }"
        : "=r"(smb) : "l"(sh));

    const int tid  = threadIdx.x;
    const int lane = tid & 31;
    const int wid  = tid >> 5;
    const int wm   = wid & 1;    // 2 m-positions (64 rows)
    const int wn   = wid >> 1;   // 4 n-positions (64 cols)
    const int g    = lane >> 2;
    const int c    = lane & 3;

    const int m0 = blockIdx.y * GBM;
    const int n0 = blockIdx.x * GBN;

    // A staging: thread covers rows (tid>>3)+32p, k = 4*(tid&7)+j
    const int a_row = tid >> 3;
    const int ak4   = tid & 7;
    const int a_ks  = ak4 >> 1;
    const int a_rh  = 2 * (ak4 & 1);

    float acc[4][8][4];
#pragma unroll
    for (int i = 0; i < 4; i++)
#pragma unroll
        for (int j = 0; j < 8; j++)
#pragma unroll
            for (int l = 0; l < 4; l++) acc[i][j][l] = 0.f;

    float4 ra[4];

    auto ldgA = [&](int k0) {
#pragma unroll
        for (int p = 0; p < 4; p++)
            ra[p] = *reinterpret_cast<const float4*>(
                &A[(size_t)(m0 + a_row + 32 * p) * K + k0 + ak4 * 4]);
    };
    auto stsA = [&](int s) {
        float* dst = sh + s * STAGE_FLOATS;
#pragma unroll
        for (int p = 0; p < 4; p++) {
            int m  = a_row + 32 * p;
            int mf = m >> 4, r16 = m & 15;
            int basef = (mf * 4 + a_ks) * 132 + (r16 & 7) * 16 + (r16 >> 3) + a_rh;
            dst[basef + 0]  = ra[p].x;
            dst[basef + 4]  = ra[p].y;
            dst[basef + 8]  = ra[p].z;
            dst[basef + 12] = ra[p].w;
        }
    };
    // B: cp.async 8 chunks/thread; chunk ch -> k=ch>>6 (0..31), n4=ch&63
    auto cpB = [&](int s, int k0) {
        uint32_t sb = smb + (uint32_t)(s * STAGE_FLOATS + AFRAG_FLOATS) * 4;
#pragma unroll
        for (int p = 0; p < 8; p++) {
            int ch  = p * 256 + tid;
            int k   = ch >> 6;
            int n4  = ch & 63;
            int row = ((k >> 3) * 2 + ((k >> 2) & 1)) * 4 + (k & 3);
            cp16(sb + (uint32_t)(row * 264 + n4 * 4) * 4,
                 &W[(size_t)(k0 + k) * N + n0 + n4 * 4]);
        }
    };
    auto compute = [&](int s, int ks) {
        const float* as_ = sh + s * STAGE_FLOATS;
        const float* bs_ = as_ + AFRAG_FLOATS;
        uint32_t af[4][4], bfr[8][2];
#pragma unroll
        for (int mf = 0; mf < 4; mf++) {
            float4 v = *reinterpret_cast<const float4*>(
                as_ + ((wm * 4 + mf) * 4 + ks) * 132 + lane * 4);
            af[mf][0] = __float_as_uint(v.x);
            af[mf][1] = __float_as_uint(v.y);
            af[mf][2] = __float_as_uint(v.z);
            af[mf][3] = __float_as_uint(v.w);
        }
        const int bcol = wn * 64 + g;
#pragma unroll
        for (int nf = 0; nf < 8; nf++) {
            bfr[nf][0] = __float_as_uint(bs_[(ks * 8 + c) * 264 + bcol + nf * 8]);
            bfr[nf][1] = __float_as_uint(bs_[(ks * 8 + 4 + c) * 264 + bcol + nf * 8]);
        }
#pragma unroll
        for (int mf = 0; mf < 4; mf++)
#pragma unroll
            for (int nf = 0; nf < 8; nf++)
                mma_tf32(acc[mf][nf], af[mf], bfr[nf]);
    };

    const int niter = K / GBK;

    // prologue
    cpB(0, 0);
    asm volatile("cp.async.commit_group;");
    ldgA(0);
    stsA(0);

    for (int it = 0; it < niter; it++) {
        const int s = it & 1;
        const bool pre = (it + 1 < niter);
        const int k0n = (it + 1) * GBK;

        asm volatile("cp.async.wait_group 0;");   // B(s) arrived
        __syncthreads();                          // A(s) visible; stage s^1 free

        if (pre) {
            cpB(s ^ 1, k0n);
            asm volatile("cp.async.commit_group;");
            ldgA(k0n);
        }
        compute(s, 0);
        if (pre) stsA(s ^ 1);
        compute(s, 1);
        compute(s, 2);
        compute(s, 3);
    }

    // epilogue: acc + bias -> C
#pragma unroll
    for (int mf = 0; mf < 4; mf++) {
        int r = m0 + wm * 64 + mf * 16 + g;
#pragma unroll
        for (int nf = 0; nf < 8; nf++) {
            int col = n0 + wn * 64 + nf * 8 + c * 2;
            float b0v = bias[col], b1v = bias[col + 1];
            *reinterpret_cast<float2*>(&C[(size_t)r * N + col]) =
                make_float2(acc[mf][nf][0] + b0v, acc[mf][nf][1] + b1v);
            *reinterpret_cast<float2*>(&C[(size_t)(r + 8) * N + col]) =
                make_float2(acc[mf][nf][2] + b0v, acc[mf][nf][3] + b1v);
        }
    }
}

// ===========================================================================
// Tensor-core flash attention (tf32 mma.sync) — unchanged from R9 (passing)
// ===========================================================================
#define AT_BM 128
#define AT_BN 64
#define KSTR 132
#define VSTR 136
#define PSTR 68
#define SM_QF 0
#define SM_K0 16384
#define SM_K1 (16384 + 8448)
#define SM_V  (16384 + 16896)
#define SM_P  (16384 + 16896 + 8704)
#define AT_SMEM_FLOATS (16384 + 16896 + 8704 + 8704)
#define AT_SMEM_BYTES  (AT_SMEM_FLOATS * 4)

__global__ __launch_bounds__(256) void flash_attn_tc_kernel(
    const float* __restrict__ qkv, float* __restrict__ att)
{
    extern __shared__ float sm[];
    const int tid  = threadIdx.x;
    const int lane = tid & 31;
    const int w    = tid >> 5;
    const int g    = lane >> 2;
    const int c    = lane & 3;
    const int qb   = (int)gridDim.x - 1 - (int)blockIdx.x;
    const int h    = blockIdx.y;
    const int b    = blockIdx.z;
    const int q0   = qb * AT_BM;
    const size_t base = (size_t)b * SS_ * N_QKV + (size_t)h * HD;
    const float scale = 0.08838834764831845f;

    uint32_t smb;
    asm("{ .reg .u64 t; cvta.to.shared.u64 t, %1; cvt.u32.u64 %0, t; }" : "=r"(smb) : "l"(sm));

#pragma unroll
    for (int i = 0; i < 16; i++) {
        int id = tid + i * 256;
        int r  = id >> 5;
        int c4 = (id & 31) << 2;
        float4 v = *reinterpret_cast<const float4*>(&qkv[base + (size_t)(q0 + r) * N_QKV + c4]);
        int rb = r >> 4, rr = r & 15, gg = rr & 7, half = rr >> 3;
        int ks = c4 >> 3, khalf = (c4 >> 2) & 1;
        int reg = half + 2 * khalf;
        int ba = ((rb * 16 + ks) * 32) * 4 + reg;
        float vv[4] = {v.x, v.y, v.z, v.w};
#pragma unroll
        for (int j = 0; j < 4; j++)
            sm[SM_QF + ba + (gg * 4 + j) * 4] = __uint_as_float(f2tf(vv[j] * scale));
    }

    float o[16][4];
#pragma unroll
    for (int nt = 0; nt < 16; nt++)
#pragma unroll
        for (int l = 0; l < 4; l++) o[nt][l] = 0.f;
    float m0 = -INFINITY, m1 = -INFINITY, l0 = 0.f, l1 = 0.f;

    const int r0 = q0 + w * 16 + g;
    const int nkb = 2 * qb + 2;
    const uint32_t pbase = SM_P + w * (16 * PSTR);

#pragma unroll
    for (int i = 0; i < 8; i++) {
        int id = tid + i * 256;
        int row = id >> 5, c16 = (id & 31) << 2;
        cp16(smb + (uint32_t)(SM_K0 + row * KSTR + c16) * 4,
             &qkv[base + (size_t)row * N_QKV + DD + c16]);
    }
    asm volatile("cp.async.commit_group;");

    for (int kb = 0; kb < nkb; kb++) {
        const int k0 = kb * AT_BN;
        const int sK = (kb & 1) ? SM_K1 : SM_K0;

#pragma unroll
        for (int i = 0; i < 8; i++) {
            int id = tid + i * 256;
            int row = id >> 5, c16 = (id & 31) << 2;
            cp16(smb + (uint32_t)(SM_V + row * VSTR + c16) * 4,
                 &qkv[base + (size_t)(k0 + row) * N_QKV + 2 * DD + c16]);
        }
        asm volatile("cp.async.commit_group;");
        asm volatile("cp.async.wait_group 1;");
        __syncthreads();

        float s[8][4];
#pragma unroll
        for (int nt = 0; nt < 8; nt++)
#pragma unroll
            for (int l = 0; l < 4; l++) s[nt][l] = 0.f;

#pragma unroll
        for (int ks = 0; ks < 16; ks++) {
            float4 qa = *reinterpret_cast<const float4*>(&sm[SM_QF + ((w * 16 + ks) * 32 + lane) * 4]);
            uint32_t a[4] = {__float_as_uint(qa.x), __float_as_uint(qa.y),
                             __float_as_uint(qa.z), __float_as_uint(qa.w)};
#pragma unroll
            for (int nt = 0; nt < 8; nt++) {
                const float* kp = &sm[sK + (nt * 8 + g) * KSTR + ks * 8 + c];
                uint32_t bfr[2] = {f2tf(kp[0]), f2tf(kp[4])};
                mma_tf32(s[nt], a, bfr);
            }
        }

        if (kb + 1 < nkb) {
            const int sKn = (kb & 1) ? SM_K0 : SM_K1;
            const int k0n = (kb + 1) * AT_BN;
#pragma unroll
            for (int i = 0; i < 8; i++) {
                int id = tid + i * 256;
                int row = id >> 5, c16 = (id & 31) << 2;
                cp16(smb + (uint32_t)(sKn + row * KSTR + c16) * 4,
                     &qkv[base + (size_t)(k0n + row) * N_QKV + DD + c16]);
            }
        }
        asm volatile("cp.async.commit_group;");

        if (k0 + 63 > q0 + w * 16) {
#pragma unroll
            for (int nt = 0; nt < 8; nt++) {
                int col = k0 + nt * 8 + 2 * c;
                if (col     > r0)     s[nt][0] = -INFINITY;
                if (col + 1 > r0)     s[nt][1] = -INFINITY;
                if (col     > r0 + 8) s[nt][2] = -INFINITY;
                if (col + 1 > r0 + 8) s[nt][3] = -INFINITY;
            }
        }

        float mt0 = -INFINITY, mt1 = -INFINITY;
#pragma unroll
        for (int nt = 0; nt < 8; nt++) {
            mt0 = fmaxf(mt0, fmaxf(s[nt][0], s[nt][1]));
            mt1 = fmaxf(mt1, fmaxf(s[nt][2], s[nt][3]));
        }
        mt0 = fmaxf(mt0, __shfl_xor_sync(0xffffffffu, mt0, 1));
        mt0 = fmaxf(mt0, __shfl_xor_sync(0xffffffffu, mt0, 2));
        mt1 = fmaxf(mt1, __shfl_xor_sync(0xffffffffu, mt1, 1));
        mt1 = fmaxf(mt1, __shfl_xor_sync(0xffffffffu, mt1, 2));

        float mn0 = fmaxf(m0, mt0), mn1 = fmaxf(m1, mt1);
        float cr0 = __expf(m0 - mn0), cr1 = __expf(m1 - mn1);
        m0 = mn0; m1 = mn1;

        float ps0 = 0.f, ps1 = 0.f;
#pragma unroll
        for (int nt = 0; nt < 8; nt++) {
            float p00 = __expf(s[nt][0] - m0);
            float p01 = __expf(s[nt][1] - m0);
            float p10 = __expf(s[nt][2] - m1);
            float p11 = __expf(s[nt][3] - m1);
            ps0 += p00 + p01;
            ps1 += p10 + p11;
            uint2 u0 = make_uint2(f2tf(p00), f2tf(p01));
            uint2 u1 = make_uint2(f2tf(p10), f2tf(p11));
            *reinterpret_cast<uint2*>(&sm[pbase + g * PSTR + nt * 8 + 2 * c])       = u0;
            *reinterpret_cast<uint2*>(&sm[pbase + (g + 8) * PSTR + nt * 8 + 2 * c]) = u1;
        }
        ps0 += __shfl_xor_sync(0xffffffffu, ps0, 1);
        ps0 += __shfl_xor_sync(0xffffffffu, ps0, 2);
        ps1 += __shfl_xor_sync(0xffffffffu, ps1, 1);
        ps1 += __shfl_xor_sync(0xffffffffu, ps1, 2);
        l0 = l0 * cr0 + ps0;
        l1 = l1 * cr1 + ps1;

#pragma unroll
        for (int nt = 0; nt < 16; nt++) {
            o[nt][0] *= cr0; o[nt][1] *= cr0;
            o[nt][2] *= cr1; o[nt][3] *= cr1;
        }

        asm volatile("cp.async.wait_group 1;");
        __syncthreads();

#pragma unroll
        for (int ks2 = 0; ks2 < 8; ks2++) {
            uint32_t a[4];
            a[0] = __float_as_uint(sm[pbase + g * PSTR + ks2 * 8 + c]);
            a[1] = __float_as_uint(sm[pbase + (g + 8) * PSTR + ks2 * 8 + c]);
            a[2] = __float_as_uint(sm[pbase + g * PSTR + ks2 * 8 + c + 4]);
            a[3] = __float_as_uint(sm[pbase + (g + 8) * PSTR + ks2 * 8 + c + 4]);
#pragma unroll
            for (int nt = 0; nt < 16; nt++) {
                uint32_t bfr[2] = {
                    __float_as_uint(sm[SM_V + (ks2 * 8 + c) * VSTR + nt * 8 + g]),
                    __float_as_uint(sm[SM_V + (ks2 * 8 + c + 4) * VSTR + nt * 8 + g])};
                mma_tf32(o[nt], a, bfr);
            }
        }
        __syncthreads();
    }

    float il0 = 1.f / l0, il1 = 1.f / l1;
    size_t ob = ((size_t)(b * SS_) + q0 + w * 16) * DD + (size_t)h * HD;
#pragma unroll
    for (int nt = 0; nt < 16; nt++) {
        int col = nt * 8 + 2 * c;
        uint2 w0 = make_uint2(f2tf(o[nt][0] * il0), f2tf(o[nt][1] * il0));
        uint2 w1 = make_uint2(f2tf(o[nt][2] * il1), f2tf(o[nt][3] * il1));
        *reinterpret_cast<uint2*>(&att[ob + (size_t)g * DD + col])       = w0;
        *reinterpret_cast<uint2*>(&att[ob + (size_t)(g + 8) * DD + col]) = w1;
    }
}

// ===========================================================================
// Launch
// ===========================================================================
extern "C" void kernel_launch(void* const* d_in, const int* in_sizes, int n_in,
                              void* d_out, int out_size)
{
    const float* x      = (const float*)d_in[0];
    const float* W_qkv  = (const float*)d_in[1];
    const float* b_qkv  = (const float*)d_in[2];
    const float* W_out  = (const float*)d_in[3];
    const float* b_out  = (const float*)d_in[4];
    float* out          = (float*)d_out;

    float *qkv_ptr, *att_ptr, *x_ptr, *w1_ptr, *w2_ptr;
    cudaGetSymbolAddress((void**)&qkv_ptr, g_qkv);
    cudaGetSymbolAddress((void**)&att_ptr, g_att);
    cudaGetSymbolAddress((void**)&x_ptr,  g_x);
    cudaGetSymbolAddress((void**)&w1_ptr, g_w1);
    cudaGetSymbolAddress((void**)&w2_ptr, g_w2);

    cudaFuncSetAttribute(gemm_tf32_kernel,
                         cudaFuncAttributeMaxDynamicSharedMemorySize, GEMM_SMEM_BYTES);
    cudaFuncSetAttribute(flash_attn_tc_kernel,
                         cudaFuncAttributeMaxDynamicSharedMemorySize, AT_SMEM_BYTES);

    // Pre-round operands to tf32 (rna) once
    cvt_tf32_kernel<<<592, 256>>>(x,     x_ptr,  M_TOT * DD / 4);
    cvt_tf32_kernel<<<592, 256>>>(W_qkv, w1_ptr, DD * N_QKV / 4);
    cvt_tf32_kernel<<<592, 256>>>(W_out, w2_ptr, DD * DD / 4);

    // QKV projection: [4096,2048] @ [2048,6144]
    gemm_tf32_kernel<<<dim3(N_QKV / GBN, M_TOT / GBM), 256, GEMM_SMEM_BYTES>>>(
        x_ptr, w1_ptr, b_qkv, qkv_ptr, M_TOT, N_QKV, DD);

    // Fused causal attention (tensor-core)
    flash_attn_tc_kernel<<<dim3(SS_ / AT_BM, HH, BB), 256, AT_SMEM_BYTES>>>(qkv_ptr, att_ptr);

    // Output projection: [4096,2048] @ [2048,2048]
    gemm_tf32_kernel<<<dim3(DD / GBN, M_TOT / GBM), 256, GEMM_SMEM_BYTES>>>(
        att_ptr, w2_ptr, b_out, out, M_TOT, DD, DD);
}

// round 12
// speedup vs baseline: 1.1920x; 1.1920x over previous
#include <cuda_runtime.h>
#include <math.h>
#include <stdint.h>

#define BB 2
#define SS_ 2048
#define DD 2048
#define HH 16
#define HD 128
#define M_TOT (BB * SS_)     // 4096
#define N_QKV (3 * DD)       // 6144

__device__ float g_qkv[M_TOT * N_QKV];     // raw qkv rows
__device__ float g_att[M_TOT * DD];        // attention out rows (tf32-rounded)
__device__ float g_xfm [M_TOT * DD];       // x, fragment-major A
__device__ float g_attfm[M_TOT * DD];      // att, fragment-major A
__device__ float g_w1fm[DD * N_QKV];       // W_qkv, fragment-major B
__device__ float g_w2fm[DD * DD];          // W_out, fragment-major B

__device__ __forceinline__ uint32_t f2tf(float f) {
    uint32_t u;
    asm("cvt.rna.tf32.f32 %0, %1;" : "=r"(u) : "f"(f));
    return u;
}

__device__ __forceinline__ void mma_tf32(float* d, const uint32_t* a, const uint32_t* b) {
    asm volatile(
        "mma.sync.aligned.m16n8k8.row.col.f32.tf32.tf32.f32 "
        "{%0,%1,%2,%3}, {%4,%5,%6,%7}, {%8,%9}, {%0,%1,%2,%3};\n"
        : "+f"(d[0]), "+f"(d[1]), "+f"(d[2]), "+f"(d[3])
        : "r"(a[0]), "r"(a[1]), "r"(a[2]), "r"(a[3]), "r"(b[0]), "r"(b[1]));
}

__device__ __forceinline__ void cp16(uint32_t saddr, const float* gptr) {
    asm volatile("cp.async.cg.shared.global [%0], [%1], 16;" :: "r"(saddr), "l"(gptr));
}

// ===========================================================================
// Prep A: row-major [M,K] fp32 -> fragment-major tf32 blocks.
// Block (mb,kc) -> 4096 floats: frag f = mf*4+ks (128 floats each):
//   pos g*16+c*4+t = A[mb*128 + mf*16 + (t&1)*8 + g][kc*32 + ks*8 + (t>>1)*4 + c]
// ===========================================================================
__global__ __launch_bounds__(256) void prep_a_kernel(
    const float* __restrict__ src, float* __restrict__ dst, int K)
{
    __shared__ float tile[128 * 36];
    const int tid = threadIdx.x;
    const int nkc = K >> 5;
    const int mb = blockIdx.x / nkc;
    const int kc = blockIdx.x % nkc;
    const float* s0 = src + (size_t)mb * 128 * K + kc * 32;

#pragma unroll
    for (int p = 0; p < 4; p++) {
        int id = tid + p * 256;          // float4 index 0..1023
        int row = id >> 3, c4 = (id & 7) << 2;
        float4 v = *reinterpret_cast<const float4*>(s0 + (size_t)row * K + c4);
        float* t = &tile[row * 36 + c4];
        t[0] = v.x; t[1] = v.y; t[2] = v.z; t[3] = v.w;
    }
    __syncthreads();

    float* d0 = dst + (size_t)blockIdx.x * 4096;
#pragma unroll
    for (int p = 0; p < 4; p++) {
        int q = tid + p * 256;           // output float4 index
        int f = q >> 5;
        int l = q & 31;
        int g = l >> 2, c = l & 3;
        int mf = f >> 2, ks = f & 3;
        const float* tl = &tile[(mf * 16 + g) * 36 + ks * 8 + c];
        uint4 o;
        o.x = f2tf(tl[0]);               // t=0: row g,   k c
        o.y = f2tf(tl[8 * 36]);          // t=1: row g+8, k c
        o.z = f2tf(tl[4]);               // t=2: row g,   k c+4
        o.w = f2tf(tl[8 * 36 + 4]);      // t=3: row g+8, k c+4
        *reinterpret_cast<uint4*>(d0 + q * 4) = o;
    }
}

// ===========================================================================
// Prep B: row-major W[K,N] fp32 -> fragment-major tf32 blocks.
// Block (nb,kc) -> 4096 floats: frag fb = ks*16+n8 (64 floats each):
//   pos g*8+c*2+u = W[kc*32 + ks*8 + u*4 + c][nb*128 + n8*8 + g]
// ===========================================================================
__global__ __launch_bounds__(256) void prep_b_kernel(
    const float* __restrict__ src, float* __restrict__ dst, int N, int K)
{
    __shared__ float tile[32 * 132];
    const int tid = threadIdx.x;
    const int nkc = K >> 5;
    const int nb = blockIdx.x / nkc;
    const int kc = blockIdx.x % nkc;
    const float* s0 = src + (size_t)(kc * 32) * N + nb * 128;

#pragma unroll
    for (int p = 0; p < 4; p++) {
        int id = tid + p * 256;
        int k = id >> 5, n4 = (id & 31) << 2;
        float4 v = *reinterpret_cast<const float4*>(s0 + (size_t)k * N + n4);
        *reinterpret_cast<float4*>(&tile[k * 132 + n4]) = v;
    }
    __syncthreads();

    float* d0 = dst + (size_t)blockIdx.x * 4096;
#pragma unroll
    for (int p = 0; p < 4; p++) {
        int q = tid + p * 256;           // output float4 index
        int fb = q >> 4;
        int ks = fb >> 4, n8 = fb & 15;
        int o4 = (q & 15) << 2;          // base offset in frag (g*8+c*2+u)
        uint4 o;
        uint32_t* ov = reinterpret_cast<uint32_t*>(&o);
#pragma unroll
        for (int i = 0; i < 4; i++) {
            int off = o4 + i;
            int g = off >> 3, c = (off & 7) >> 1, u = off & 1;
            ov[i] = f2tf(tile[(ks * 8 + u * 4 + c) * 132 + n8 * 8 + g]);
        }
        *reinterpret_cast<uint4*>(d0 + q * 4) = o;
    }
}

// ===========================================================================
// TF32 mma.sync GEMM, fragment-major cp.async staging (no LDG/STS in loop).
// Block 128x128, 8 warps (2m x 4n), warp tile 64x32. Consume as R9:
// A LDS.128 (132-float frag stride), B LDS.64 (68-float frag stride — padded
// so every frag base is 16B-aligned for cp.async; 66 was the R11 trap).
// ===========================================================================
#define AFRAG_FLOATS 4224                 // 32 frags * 132  (528 B, 16-aligned)
#define BFRAG_FLOATS 4352                 // 64 frags * 68   (272 B, 16-aligned)
#define STAGE_FLOATS (AFRAG_FLOATS + BFRAG_FLOATS)
#define GEMM_SMEM_BYTES (2 * STAGE_FLOATS * 4)   // 68608

__global__ __launch_bounds__(256) void gemm_fm_kernel(
    const float* __restrict__ Afm, const float* __restrict__ Bfm,
    const float* __restrict__ bias, float* __restrict__ C,
    int M, int N, int K)
{
    extern __shared__ float sh[];
    uint32_t smb;
    asm("{ .reg .u64 t; cvta.to.shared.u64 t, %1; cvt.u32.u64 %0, t; }"
        : "=r"(smb) : "l"(sh));

    const int tid  = threadIdx.x;
    const int lane = tid & 31;
    const int wid  = tid >> 5;
    const int wm   = wid & 1;
    const int wn   = wid >> 1;
    const int g    = lane >> 2;
    const int c    = lane & 3;

    const int nkc = K >> 5;
    const int mb  = blockIdx.y;
    const int nb  = blockIdx.x;
    const float* Ab = Afm + (size_t)mb * nkc * 4096;
    const float* Bb = Bfm + (size_t)nb * nkc * 4096;

    float acc[4][4][4];
#pragma unroll
    for (int i = 0; i < 4; i++)
#pragma unroll
        for (int j = 0; j < 4; j++)
#pragma unroll
            for (int l = 0; l < 4; l++) acc[i][j][l] = 0.f;

    auto stage_cp = [&](int s, int kc) {
        const float* ag = Ab + (size_t)kc * 4096;
        const float* bg = Bb + (size_t)kc * 4096;
        uint32_t sa = smb + (uint32_t)(s * STAGE_FLOATS) * 4;
        uint32_t sb = sa + AFRAG_FLOATS * 4;
#pragma unroll
        for (int p = 0; p < 4; p++) {
            int ch = tid + p * 256;              // A chunk 0..1023
            int f = ch >> 5, off = ch & 31;
            cp16(sa + (uint32_t)(f * 528 + off * 16), ag + ch * 4);
        }
#pragma unroll
        for (int p = 0; p < 4; p++) {
            int ch = tid + p * 256;              // B chunk 0..1023
            int fb = ch >> 4, off = ch & 15;
            cp16(sb + (uint32_t)(fb * 272 + off * 16), bg + ch * 4);
        }
    };

    auto compute = [&](int s, int ks) {
        const float* as_ = sh + s * STAGE_FLOATS;
        const float* bs_ = as_ + AFRAG_FLOATS;
        uint32_t af[4][4], bfr[4][2];
#pragma unroll
        for (int mf = 0; mf < 4; mf++) {
            float4 v = *reinterpret_cast<const float4*>(
                as_ + ((wm * 4 + mf) * 4 + ks) * 132 + lane * 4);
            af[mf][0] = __float_as_uint(v.x);
            af[mf][1] = __float_as_uint(v.y);
            af[mf][2] = __float_as_uint(v.z);
            af[mf][3] = __float_as_uint(v.w);
        }
#pragma unroll
        for (int nf = 0; nf < 4; nf++) {
            float2 v = *reinterpret_cast<const float2*>(
                bs_ + (ks * 16 + wn * 4 + nf) * 68 + lane * 2);
            bfr[nf][0] = __float_as_uint(v.x);
            bfr[nf][1] = __float_as_uint(v.y);
        }
#pragma unroll
        for (int mf = 0; mf < 4; mf++)
#pragma unroll
            for (int nf = 0; nf < 4; nf++)
                mma_tf32(acc[mf][nf], af[mf], bfr[nf]);
    };

    const int niter = nkc;

    stage_cp(0, 0);
    asm volatile("cp.async.commit_group;");

    for (int it = 0; it < niter; it++) {
        const int s = it & 1;
        asm volatile("cp.async.wait_group 0;");
        __syncthreads();
        if (it + 1 < niter) {
            stage_cp(s ^ 1, it + 1);
            asm volatile("cp.async.commit_group;");
        }
        compute(s, 0);
        compute(s, 1);
        compute(s, 2);
        compute(s, 3);
    }

    // epilogue: acc + bias -> C
    const int m0 = mb * 128;
    const int n0 = nb * 128;
#pragma unroll
    for (int mf = 0; mf < 4; mf++) {
        int r = m0 + wm * 64 + mf * 16 + g;
#pragma unroll
        for (int nf = 0; nf < 4; nf++) {
            int col = n0 + wn * 32 + nf * 8 + c * 2;
            float b0v = bias[col], b1v = bias[col + 1];
            *reinterpret_cast<float2*>(&C[(size_t)r * N + col]) =
                make_float2(acc[mf][nf][0] + b0v, acc[mf][nf][1] + b1v);
            *reinterpret_cast<float2*>(&C[(size_t)(r + 8) * N + col]) =
                make_float2(acc[mf][nf][2] + b0v, acc[mf][nf][3] + b1v);
        }
    }
}

// ===========================================================================
// Tensor-core flash attention (tf32 mma.sync) — unchanged from R9 (passing)
// ===========================================================================
#define AT_BM 128
#define AT_BN 64
#define KSTR 132
#define VSTR 136
#define PSTR 68
#define SM_QF 0
#define SM_K0 16384
#define SM_K1 (16384 + 8448)
#define SM_V  (16384 + 16896)
#define SM_P  (16384 + 16896 + 8704)
#define AT_SMEM_FLOATS (16384 + 16896 + 8704 + 8704)
#define AT_SMEM_BYTES  (AT_SMEM_FLOATS * 4)

__global__ __launch_bounds__(256) void flash_attn_tc_kernel(
    const float* __restrict__ qkv, float* __restrict__ att)
{
    extern __shared__ float sm[];
    const int tid  = threadIdx.x;
    const int lane = tid & 31;
    const int w    = tid >> 5;
    const int g    = lane >> 2;
    const int c    = lane & 3;
    const int qb   = (int)gridDim.x - 1 - (int)blockIdx.x;
    const int h    = blockIdx.y;
    const int b    = blockIdx.z;
    const int q0   = qb * AT_BM;
    const size_t base = (size_t)b * SS_ * N_QKV + (size_t)h * HD;
    const float scale = 0.08838834764831845f;

    uint32_t smb;
    asm("{ .reg .u64 t; cvta.to.shared.u64 t, %1; cvt.u32.u64 %0, t; }" : "=r"(smb) : "l"(sm));

#pragma unroll
    for (int i = 0; i < 16; i++) {
        int id = tid + i * 256;
        int r  = id >> 5;
        int c4 = (id & 31) << 2;
        float4 v = *reinterpret_cast<const float4*>(&qkv[base + (size_t)(q0 + r) * N_QKV + c4]);
        int rb = r >> 4, rr = r & 15, gg = rr & 7, half = rr >> 3;
        int ks = c4 >> 3, khalf = (c4 >> 2) & 1;
        int reg = half + 2 * khalf;
        int ba = ((rb * 16 + ks) * 32) * 4 + reg;
        float vv[4] = {v.x, v.y, v.z, v.w};
#pragma unroll
        for (int j = 0; j < 4; j++)
            sm[SM_QF + ba + (gg * 4 + j) * 4] = __uint_as_float(f2tf(vv[j] * scale));
    }

    float o[16][4];
#pragma unroll
    for (int nt = 0; nt < 16; nt++)
#pragma unroll
        for (int l = 0; l < 4; l++) o[nt][l] = 0.f;
    float m0 = -INFINITY, m1 = -INFINITY, l0 = 0.f, l1 = 0.f;

    const int r0 = q0 + w * 16 + g;
    const int nkb = 2 * qb + 2;
    const uint32_t pbase = SM_P + w * (16 * PSTR);

#pragma unroll
    for (int i = 0; i < 8; i++) {
        int id = tid + i * 256;
        int row = id >> 5, c16 = (id & 31) << 2;
        cp16(smb + (uint32_t)(SM_K0 + row * KSTR + c16) * 4,
             &qkv[base + (size_t)row * N_QKV + DD + c16]);
    }
    asm volatile("cp.async.commit_group;");

    for (int kb = 0; kb < nkb; kb++) {
        const int k0 = kb * AT_BN;
        const int sK = (kb & 1) ? SM_K1 : SM_K0;

#pragma unroll
        for (int i = 0; i < 8; i++) {
            int id = tid + i * 256;
            int row = id >> 5, c16 = (id & 31) << 2;
            cp16(smb + (uint32_t)(SM_V + row * VSTR + c16) * 4,
                 &qkv[base + (size_t)(k0 + row) * N_QKV + 2 * DD + c16]);
        }
        asm volatile("cp.async.commit_group;");
        asm volatile("cp.async.wait_group 1;");
        __syncthreads();

        float s[8][4];
#pragma unroll
        for (int nt = 0; nt < 8; nt++)
#pragma unroll
            for (int l = 0; l < 4; l++) s[nt][l] = 0.f;

#pragma unroll
        for (int ks = 0; ks < 16; ks++) {
            float4 qa = *reinterpret_cast<const float4*>(&sm[SM_QF + ((w * 16 + ks) * 32 + lane) * 4]);
            uint32_t a[4] = {__float_as_uint(qa.x), __float_as_uint(qa.y),
                             __float_as_uint(qa.z), __float_as_uint(qa.w)};
#pragma unroll
            for (int nt = 0; nt < 8; nt++) {
                const float* kp = &sm[sK + (nt * 8 + g) * KSTR + ks * 8 + c];
                uint32_t bfr[2] = {f2tf(kp[0]), f2tf(kp[4])};
                mma_tf32(s[nt], a, bfr);
            }
        }

        if (kb + 1 < nkb) {
            const int sKn = (kb & 1) ? SM_K0 : SM_K1;
            const int k0n = (kb + 1) * AT_BN;
#pragma unroll
            for (int i = 0; i < 8; i++) {
                int id = tid + i * 256;
                int row = id >> 5, c16 = (id & 31) << 2;
                cp16(smb + (uint32_t)(sKn + row * KSTR + c16) * 4,
                     &qkv[base + (size_t)(k0n + row) * N_QKV + DD + c16]);
            }
        }
        asm volatile("cp.async.commit_group;");

        if (k0 + 63 > q0 + w * 16) {
#pragma unroll
            for (int nt = 0; nt < 8; nt++) {
                int col = k0 + nt * 8 + 2 * c;
                if (col     > r0)     s[nt][0] = -INFINITY;
                if (col + 1 > r0)     s[nt][1] = -INFINITY;
                if (col     > r0 + 8) s[nt][2] = -INFINITY;
                if (col + 1 > r0 + 8) s[nt][3] = -INFINITY;
            }
        }

        float mt0 = -INFINITY, mt1 = -INFINITY;
#pragma unroll
        for (int nt = 0; nt < 8; nt++) {
            mt0 = fmaxf(mt0, fmaxf(s[nt][0], s[nt][1]));
            mt1 = fmaxf(mt1, fmaxf(s[nt][2], s[nt][3]));
        }
        mt0 = fmaxf(mt0, __shfl_xor_sync(0xffffffffu, mt0, 1));
        mt0 = fmaxf(mt0, __shfl_xor_sync(0xffffffffu, mt0, 2));
        mt1 = fmaxf(mt1, __shfl_xor_sync(0xffffffffu, mt1, 1));
        mt1 = fmaxf(mt1, __shfl_xor_sync(0xffffffffu, mt1, 2));

        float mn0 = fmaxf(m0, mt0), mn1 = fmaxf(m1, mt1);
        float cr0 = __expf(m0 - mn0), cr1 = __expf(m1 - mn1);
        m0 = mn0; m1 = mn1;

        float ps0 = 0.f, ps1 = 0.f;
#pragma unroll
        for (int nt = 0; nt < 8; nt++) {
            float p00 = __expf(s[nt][0] - m0);
            float p01 = __expf(s[nt][1] - m0);
            float p10 = __expf(s[nt][2] - m1);
            float p11 = __expf(s[nt][3] - m1);
            ps0 += p00 + p01;
            ps1 += p10 + p11;
            uint2 u0 = make_uint2(f2tf(p00), f2tf(p01));
            uint2 u1 = make_uint2(f2tf(p10), f2tf(p11));
            *reinterpret_cast<uint2*>(&sm[pbase + g * PSTR + nt * 8 + 2 * c])       = u0;
            *reinterpret_cast<uint2*>(&sm[pbase + (g + 8) * PSTR + nt * 8 + 2 * c]) = u1;
        }
        ps0 += __shfl_xor_sync(0xffffffffu, ps0, 1);
        ps0 += __shfl_xor_sync(0xffffffffu, ps0, 2);
        ps1 += __shfl_xor_sync(0xffffffffu, ps1, 1);
        ps1 += __shfl_xor_sync(0xffffffffu, ps1, 2);
        l0 = l0 * cr0 + ps0;
        l1 = l1 * cr1 + ps1;

#pragma unroll
        for (int nt = 0; nt < 16; nt++) {
            o[nt][0] *= cr0; o[nt][1] *= cr0;
            o[nt][2] *= cr1; o[nt][3] *= cr1;
        }

        asm volatile("cp.async.wait_group 1;");
        __syncthreads();

#pragma unroll
        for (int ks2 = 0; ks2 < 8; ks2++) {
            uint32_t a[4];
            a[0] = __float_as_uint(sm[pbase + g * PSTR + ks2 * 8 + c]);
            a[1] = __float_as_uint(sm[pbase + (g + 8) * PSTR + ks2 * 8 + c]);
            a[2] = __float_as_uint(sm[pbase + g * PSTR + ks2 * 8 + c + 4]);
            a[3] = __float_as_uint(sm[pbase + (g + 8) * PSTR + ks2 * 8 + c + 4]);
#pragma unroll
            for (int nt = 0; nt < 16; nt++) {
                uint32_t bfr[2] = {
                    __float_as_uint(sm[SM_V + (ks2 * 8 + c) * VSTR + nt * 8 + g]),
                    __float_as_uint(sm[SM_V + (ks2 * 8 + c + 4) * VSTR + nt * 8 + g])};
                mma_tf32(o[nt], a, bfr);
            }
        }
        __syncthreads();
    }

    float il0 = 1.f / l0, il1 = 1.f / l1;
    size_t ob = ((size_t)(b * SS_) + q0 + w * 16) * DD + (size_t)h * HD;
#pragma unroll
    for (int nt = 0; nt < 16; nt++) {
        int col = nt * 8 + 2 * c;
        uint2 w0 = make_uint2(f2tf(o[nt][0] * il0), f2tf(o[nt][1] * il0));
        uint2 w1 = make_uint2(f2tf(o[nt][2] * il1), f2tf(o[nt][3] * il1));
        *reinterpret_cast<uint2*>(&att[ob + (size_t)g * DD + col])       = w0;
        *reinterpret_cast<uint2*>(&att[ob + (size_t)(g + 8) * DD + col]) = w1;
    }
}

// ===========================================================================
// Launch
// ===========================================================================
extern "C" void kernel_launch(void* const* d_in, const int* in_sizes, int n_in,
                              void* d_out, int out_size)
{
    const float* x      = (const float*)d_in[0];
    const float* W_qkv  = (const float*)d_in[1];
    const float* b_qkv  = (const float*)d_in[2];
    const float* W_out  = (const float*)d_in[3];
    const float* b_out  = (const float*)d_in[4];
    float* out          = (float*)d_out;

    float *qkv_p, *att_p, *xfm_p, *attfm_p, *w1fm_p, *w2fm_p;
    cudaGetSymbolAddress((void**)&qkv_p,   g_qkv);
    cudaGetSymbolAddress((void**)&att_p,   g_att);
    cudaGetSymbolAddress((void**)&xfm_p,   g_xfm);
    cudaGetSymbolAddress((void**)&attfm_p, g_attfm);
    cudaGetSymbolAddress((void**)&w1fm_p,  g_w1fm);
    cudaGetSymbolAddress((void**)&w2fm_p,  g_w2fm);

    cudaFuncSetAttribute(gemm_fm_kernel,
                         cudaFuncAttributeMaxDynamicSharedMemorySize, GEMM_SMEM_BYTES);
    cudaFuncSetAttribute(flash_attn_tc_kernel,
                         cudaFuncAttributeMaxDynamicSharedMemorySize, AT_SMEM_BYTES);

    // One-time operand formatting (rounds to tf32 + fragment-major layout)
    prep_a_kernel<<<(M_TOT / 128) * (DD / 32), 256>>>(x, xfm_p, DD);
    prep_b_kernel<<<(N_QKV / 128) * (DD / 32), 256>>>(W_qkv, w1fm_p, N_QKV, DD);
    prep_b_kernel<<<(DD / 128) * (DD / 32), 256>>>(W_out, w2fm_p, DD, DD);

    // QKV projection: [4096,2048] @ [2048,6144]
    gemm_fm_kernel<<<dim3(N_QKV / 128, M_TOT / 128), 256, GEMM_SMEM_BYTES>>>(
        xfm_p, w1fm_p, b_qkv, qkv_p, M_TOT, N_QKV, DD);

    // Fused causal attention (tensor-core)
    flash_attn_tc_kernel<<<dim3(SS_ / AT_BM, HH, BB), 256, AT_SMEM_BYTES>>>(qkv_p, att_p);

    // Format attention output as A for the out-projection
    prep_a_kernel<<<(M_TOT / 128) * (DD / 32), 256>>>(att_p, attfm_p, DD);

    // Output projection: [4096,2048] @ [2048,2048]
    gemm_fm_kernel<<<dim3(DD / 128, M_TOT / 128), 256, GEMM_SMEM_BYTES>>>(
        attfm_p, w2fm_p, b_out, out, M_TOT, DD, DD);
}